// round 14
// baseline (speedup 1.0000x reference)
#include <cuda_runtime.h>
#include <cuda_fp16.h>
#include <cstdint>

#define HH   768
#define WW   768
#define HID  256
#define NPIX (HH*WW)

// ---------------- scratch ----------------
__device__ uint32_t g_hxh[HH * 128];
__device__ uint32_t g_hyh[WW * 128];

// ---------------- helpers ----------------
__device__ __forceinline__ uint32_t pack_h2(float lo, float hi) {
    __half2 h = __floats2half2_rn(lo, hi);
    return *reinterpret_cast<uint32_t*>(&h);
}
__device__ __forceinline__ uint32_t hmul2u(uint32_t a, uint32_t b) {
    uint32_t d;
    asm("mul.f16x2 %0, %1, %2;" : "=r"(d) : "r"(a), "r"(b));
    return d;
}
__device__ __forceinline__ float fast_sin(float x) {
    const float INV_PI = 0.3183098861837907f;
    const float PI_HI  = 3.14159274101257324f;
    const float PI_LO  = -8.742277657347586e-8f;
    int   iq = __float2int_rn(x * INV_PI);
    float fq = (float)iq;
    float r  = fmaf(fq, -PI_HI, x);
    r        = fmaf(fq, -PI_LO, r);
    float r2 = r * r;
    float p  = fmaf(r2, 2.7183114939898219e-6f, -1.9839334836096632e-4f);
    p        = fmaf(r2, p, 8.3333293858894632e-3f);
    p        = fmaf(r2, p, -1.6666666641626524e-1f);
    p        = fmaf(r2 * r, p, r);
    return (iq & 1) ? -p : p;
}

#define MMA_F16(d, a, b0, b1) \
    asm volatile("mma.sync.aligned.m16n8k16.row.col.f32.f16.f16.f32 " \
        "{%0,%1,%2,%3}, {%4,%5,%6,%7}, {%8,%9}, {%0,%1,%2,%3};" \
        : "+f"((d)[0]), "+f"((d)[1]), "+f"((d)[2]), "+f"((d)[3]) \
        : "r"((a)[0]), "r"((a)[1]), "r"((a)[2]), "r"((a)[3]), \
          "r"(b0), "r"(b1))

#define GROUP_BAR(g) \
    asm volatile("bar.sync %0, 256;" :: "r"((g) + 1) : "memory")

// ---------------------------------------------------------------------------
// branch networks: 12 rows/block, 256 threads, grid (64, 2). unroll 8.
// ---------------------------------------------------------------------------
__global__ __launch_bounds__(256)
void branch_kernel(const float* __restrict__ x, const float* __restrict__ y,
                   const float* __restrict__ Wbx, const float* __restrict__ bbx,
                   const float* __restrict__ Wby, const float* __restrict__ bby,
                   const float* __restrict__ Wp1, const float* __restrict__ bp1,
                   const float* __restrict__ Wp2, const float* __restrict__ bp2)
{
    __shared__ float s0[12 * 256];
    __shared__ float s1[12 * 256];

    const int t  = threadIdx.x;
    const int br = blockIdx.y;
    const float* coord = br ? y   : x;
    const float* Wb    = br ? Wby : Wbx;
    const float* bb    = br ? bby : bbx;
    uint32_t*    outph = br ? g_hyh : g_hxh;
    const int r0 = blockIdx.x * 12;

    {
        float wv = Wb[t], bv = bb[t];
        #pragma unroll
        for (int r = 0; r < 12; r++)
            s0[r * 256 + t] = fast_sin(fmaf(coord[r0 + r], wv, bv));
    }
    __syncthreads();

    {
        float acc[12]; float b = bp1[t];
        #pragma unroll
        for (int r = 0; r < 12; r++) acc[r] = b;
        const float4* wrow = (const float4*)(Wp1 + (size_t)t * HID);
        #pragma unroll 8
        for (int k4 = 0; k4 < 64; k4++) {
            float4 w = wrow[k4];
            #pragma unroll
            for (int r = 0; r < 12; r++) {
                float4 h = *(const float4*)&s0[r * 256 + k4 * 4];
                acc[r] = fmaf(w.x, h.x, acc[r]); acc[r] = fmaf(w.y, h.y, acc[r]);
                acc[r] = fmaf(w.z, h.z, acc[r]); acc[r] = fmaf(w.w, h.w, acc[r]);
            }
        }
        #pragma unroll
        for (int r = 0; r < 12; r++) s1[r * 256 + t] = fast_sin(acc[r]);
    }
    __syncthreads();

    {
        float acc0[12], acc1[12];
        float b0 = bp2[t], b1 = bp2[t + 256];
        #pragma unroll
        for (int r = 0; r < 12; r++) { acc0[r] = b0; acc1[r] = b1; }
        const float4* w0row = (const float4*)(Wp2 + (size_t)t * HID);
        const float4* w1row = (const float4*)(Wp2 + (size_t)(t + 256) * HID);
        #pragma unroll 8
        for (int k4 = 0; k4 < 64; k4++) {
            float4 w0 = w0row[k4], w1 = w1row[k4];
            #pragma unroll
            for (int r = 0; r < 12; r++) {
                float4 h = *(const float4*)&s1[r * 256 + k4 * 4];
                acc0[r] = fmaf(w0.x, h.x, acc0[r]); acc0[r] = fmaf(w0.y, h.y, acc0[r]);
                acc0[r] = fmaf(w0.z, h.z, acc0[r]); acc0[r] = fmaf(w0.w, h.w, acc0[r]);
                acc1[r] = fmaf(w1.x, h.x, acc1[r]); acc1[r] = fmaf(w1.y, h.y, acc1[r]);
                acc1[r] = fmaf(w1.z, h.z, acc1[r]); acc1[r] = fmaf(w1.w, h.w, acc1[r]);
            }
        }
        #pragma unroll
        for (int r = 0; r < 12; r++)
            s0[r * 256 + t] = fast_sin(acc0[r]) + fast_sin(acc1[r]);
    }
    __syncthreads();

    for (int idx = t; idx < 12 * 64; idx += 256) {
        const int r = idx >> 6, s = idx & 63;
        const int n0 = (s >> 2) * 16 + (s & 3) * 2;
        const float* row = s0 + r * 256;
        uint2 val;
        val.x = pack_h2(row[n0],     row[n0 + 1]);
        val.y = pack_h2(row[n0 + 8], row[n0 + 9]);
        ((uint2*)outph)[(size_t)(r0 + r) * 64 + s] = val;
    }
}

// ---------------------------------------------------------------------------
// merge: persistent fp16 mma.sync m16n8k16, full N=256 B in smem, 512 threads.
// TWO independent warp-groups of 8 warps; each group runs its own instance
// stream (16i x 4j tiles) with private double-buffered stages/partials and a
// private named barrier -> group A's epilogue overlaps group B's MMA loop.
// Epilogue: sin -> fold-MMA(Wm2) -> combine 8 partials -> bm2+sigmoid -> out.
// ---------------------------------------------------------------------------
#define SMB_B     0            // 131072 B
#define HXP       136          // u32 pitch
#define GS_HX     8704         // 16 x 136 u32
#define GS_HY     2176         // 4 x 136 u32
#define GS_STAGE  (GS_HX + GS_HY)          // 10880
#define SMB_STG   131072                   // [g][s] stages: 4 x 10880 = 43520
#define SMB_BM1   174592                   // 1024 B
#define SMB_BF    175616                   // 4096 B
#define SMB_PT    179712                   // [g][b] 4 x 6144 = 24576
#define SMB_TOT   204288

#define N_ITILES 48
#define N_JTILES 192           // 768/4
#define INSTANCES (N_ITILES * N_JTILES)    // 9216
#define STREAMS   296          // 148 CTAs x 2 groups

__global__ __launch_bounds__(512, 1)
void merge_kernel(const float* __restrict__ Wm1, const float* __restrict__ bm1,
                  const float* __restrict__ Wm2, const float* __restrict__ bm2,
                  float* __restrict__ outg)
{
    extern __shared__ __align__(16) char smem[];
    uint32_t* sBh  = (uint32_t*)(smem + SMB_B);
    float*    s_b1 = (float*)(smem + SMB_BM1);
    uint2*    s_bf = (uint2*)(smem + SMB_BF);

    const int tid  = threadIdx.x;
    const int wid  = tid >> 5;
    const int lane = tid & 31;
    const int qk   = lane & 3;
    const int qr   = lane >> 2;
    const int g    = wid >> 3;         // warp-group 0/1
    const int nw   = wid & 7;          // n-eighth within group
    const int gtid = tid & 255;        // thread id within group

    const int cta = blockIdx.x;

    // ---- one-time: full B (Wm1) as fp16 mma fragments (paired layout) ----
    for (int idx = tid; idx < 256 * 64; idx += 512) {
        const int n  = idx >> 6;
        const int f4 = idx & 63;
        float4 v = *(const float4*)(Wm1 + (size_t)n * HID + f4 * 4);
        uint32_t h2a = pack_h2(v.x, v.y);
        uint32_t h2b = pack_h2(v.z, v.w);
        const int nt = n >> 3, qr_l = n & 7, pr = nt >> 1, sub = nt & 1;
        #pragma unroll
        for (int e = 0; e < 2; e++) {
            const int p  = 2 * f4 + e;
            const int kt = p >> 3, w8 = p & 7;
            const int slot = (((kt * 16 + pr) * 32 + qr_l * 4 + (w8 & 3)) * 4)
                             + sub * 2 + (w8 >> 2);
            sBh[slot] = e ? h2b : h2a;
        }
    }
    if (tid < 256) s_b1[tid] = bm1[tid];
    {   // fold-B fragments: [16 kt2][32 lane]
        const int kt2 = tid >> 5, ln = tid & 31;
        const int fqk = ln & 3, fqr = ln >> 2;
        uint2 v = make_uint2(0u, 0u);
        if (fqr < 3) {
            const float* wsrc = Wm2 + (size_t)fqr * HID + kt2 * 16 + 2 * fqk;
            v.x = pack_h2(wsrc[0], wsrc[1]);
            v.y = pack_h2(wsrc[8], wsrc[9]);
        }
        s_bf[kt2 * 32 + ln] = v;
    }

    // ---- prologue: stage this group's first instance into its buffer 0 ----
    const int rx = gtid >> 5, cx = gtid & 31;   // hx: rows rx, rx+8
    char* const gstage = smem + SMB_STG + g * 2 * GS_STAGE;
    {
        const int t0 = cta * 2 + g;
        const int i0 = (t0 % N_ITILES) * 16;
        const int j0 = (t0 / N_ITILES) * 4;
        uint32_t* dx = (uint32_t*)(gstage);
        uint32_t* dy = (uint32_t*)(gstage + GS_HX);
        *(uint4*)(dx + rx * HXP + cx * 4) =
            ((const uint4*)g_hxh)[(size_t)(i0 + rx) * 32 + cx];
        *(uint4*)(dx + (rx + 8) * HXP + cx * 4) =
            ((const uint4*)g_hxh)[(size_t)(i0 + rx + 8) * 32 + cx];
        if (gtid < 128)
            *(uint4*)(dy + rx * HXP + cx * 4) =
                ((const uint4*)g_hyh)[(size_t)(j0 + rx) * 32 + cx];
    }
    __syncthreads();

    int stage = 0, pbuf = 0;
    float* const gpt = (float*)(smem + SMB_PT + g * 2 * 6144);

    // ---- per-group persistent instance loop ----
    for (int inst = cta * 2 + g; inst < INSTANCES; inst += STREAMS) {
        const int i0 = (inst % N_ITILES) * 16;
        const int j0 = (inst / N_ITILES) * 4;

        // prefetch next instance into registers (overlaps MMA loop)
        const bool hasNext = (inst + STREAMS) < INSTANCES;
        uint4 phx0, phx1, phy;
        if (hasNext) {
            const int t2  = inst + STREAMS;
            const int i0n = (t2 % N_ITILES) * 16;
            const int j0n = (t2 / N_ITILES) * 4;
            phx0 = ((const uint4*)g_hxh)[(size_t)(i0n + rx) * 32 + cx];
            phx1 = ((const uint4*)g_hxh)[(size_t)(i0n + rx + 8) * 32 + cx];
            if (gtid < 128)
                phy = ((const uint4*)g_hyh)[(size_t)(j0n + rx) * 32 + cx];
        }

        uint32_t* s_hx2 = (uint32_t*)(gstage + stage * GS_STAGE);
        uint32_t* s_hy2 = (uint32_t*)(gstage + stage * GS_STAGE + GS_HX);

        // accumulators initialized with bm1 (MMA accumulates on top)
        float d[4][4][4];    // [jj][ntl][frag]; global nt = 4*nw + ntl
        #pragma unroll
        for (int ntl = 0; ntl < 4; ntl++) {
            const float b0 = s_b1[(4 * nw + ntl) * 8 + qk * 2 + 0];
            const float b1 = s_b1[(4 * nw + ntl) * 8 + qk * 2 + 1];
            #pragma unroll
            for (int jj = 0; jj < 4; jj++) {
                d[jj][ntl][0] = b0; d[jj][ntl][1] = b1;
                d[jj][ntl][2] = b0; d[jj][ntl][3] = b1;
            }
        }

        const uint32_t* hxb = s_hx2 + qr * HXP;
        const uint32_t* hyb = s_hy2;
        const uint4*    bb  = (const uint4*)sBh + lane;

        #pragma unroll 2
        for (int kt = 0; kt < 16; kt++) {
            const int so = (kt * 4 + qk) * 2;
            const uint2 x0 = *(const uint2*)(hxb + so);
            const uint2 x1 = *(const uint2*)(hxb + 8 * HXP + so);
            const uint4 Ba = bb[(kt * 16 + 2 * nw) * 32];
            const uint4 Bb = bb[(kt * 16 + 2 * nw + 1) * 32];
            #pragma unroll
            for (int jj = 0; jj < 4; jj++) {
                const uint2 yu = *(const uint2*)(hyb + jj * HXP + so);
                uint32_t a[4];
                a[0] = hmul2u(x0.x, yu.x);
                a[1] = hmul2u(x1.x, yu.x);
                a[2] = hmul2u(x0.y, yu.y);
                a[3] = hmul2u(x1.y, yu.y);
                MMA_F16(d[jj][0], a, Ba.x, Ba.y);
                MMA_F16(d[jj][1], a, Ba.z, Ba.w);
                MMA_F16(d[jj][2], a, Bb.x, Bb.y);
                MMA_F16(d[jj][3], a, Bb.z, Bb.w);
            }
        }

        // store prefetched tiles into the other stage
        if (hasNext) {
            uint32_t* dx = (uint32_t*)(gstage + (stage ^ 1) * GS_STAGE);
            uint32_t* dy = (uint32_t*)(gstage + (stage ^ 1) * GS_STAGE + GS_HX);
            *(uint4*)(dx + rx * HXP + cx * 4)       = phx0;
            *(uint4*)(dx + (rx + 8) * HXP + cx * 4) = phx1;
            if (gtid < 128)
                *(uint4*)(dy + rx * HXP + cx * 4)   = phy;
        }

        // ---- epilogue: sin -> pack -> fold-MMA over warp's N=32 ----
        float* s_pt = gpt + pbuf * 1536;
        float* pp   = s_pt + nw * 192;
        #pragma unroll
        for (int jj = 0; jj < 4; jj++) {
            float fd[4] = {0.f, 0.f, 0.f, 0.f};
            #pragma unroll
            for (int e = 0; e < 2; e++) {
                const int kt2 = 2 * nw + e;
                uint32_t a[4];
                a[0] = pack_h2(__sinf(d[jj][2 * e][0]),     __sinf(d[jj][2 * e][1]));
                a[1] = pack_h2(__sinf(d[jj][2 * e][2]),     __sinf(d[jj][2 * e][3]));
                a[2] = pack_h2(__sinf(d[jj][2 * e + 1][0]), __sinf(d[jj][2 * e + 1][1]));
                a[3] = pack_h2(__sinf(d[jj][2 * e + 1][2]), __sinf(d[jj][2 * e + 1][3]));
                uint2 bf = s_bf[kt2 * 32 + lane];
                MMA_F16(fd, a, bf.x, bf.y);
            }
            if (qk == 0) {
                pp[(jj * 16 + qr) * 3 + 0]     = fd[0];
                pp[(jj * 16 + qr) * 3 + 1]     = fd[1];
                pp[(jj * 16 + qr + 8) * 3 + 0] = fd[2];
                pp[(jj * 16 + qr + 8) * 3 + 1] = fd[3];
            } else if (qk == 1) {
                pp[(jj * 16 + qr) * 3 + 2]     = fd[0];
                pp[(jj * 16 + qr + 8) * 3 + 2] = fd[2];
            }
        }
        GROUP_BAR(g);   // s_pt[pbuf] ready + next stage ready (group-local)

        // combine 8 nw partials + bm2 + sigmoid -> out (direct)
        if (gtid < 192) {
            float v = 0.f;
            #pragma unroll
            for (int w = 0; w < 8; w++) v += s_pt[w * 192 + gtid];
            const int c   = gtid % 3;
            const int rem = gtid / 3;
            const int i   = rem & 15;
            const int j   = rem >> 4;
            v += bm2[c];
            outg[(size_t)c * NPIX + (size_t)(j0 + j) * HH + (i0 + i)] =
                __fdividef(1.0f, 1.0f + __expf(-v));
        }

        stage ^= 1; pbuf ^= 1;
    }
}

// ---------------------------------------------------------------------------
extern "C" void kernel_launch(void* const* d_in, const int* in_sizes, int n_in,
                              void* d_out, int out_size) {
    const float* x   = (const float*)d_in[0];
    const float* y   = (const float*)d_in[1];
    const float* Wbx = (const float*)d_in[2];
    const float* bbx = (const float*)d_in[3];
    const float* Wby = (const float*)d_in[4];
    const float* bby = (const float*)d_in[5];
    const float* Wp1 = (const float*)d_in[6];
    const float* bp1 = (const float*)d_in[7];
    const float* Wp2 = (const float*)d_in[8];
    const float* bp2 = (const float*)d_in[9];
    const float* Wm1 = (const float*)d_in[10];
    const float* bm1 = (const float*)d_in[11];
    const float* Wm2 = (const float*)d_in[12];
    const float* bm2 = (const float*)d_in[13];
    float* out = (float*)d_out;

    cudaFuncSetAttribute(merge_kernel,
                         cudaFuncAttributeMaxDynamicSharedMemorySize, SMB_TOT);

    branch_kernel<<<dim3(HH / 12, 2), 256>>>(x, y, Wbx, bbx, Wby, bby,
                                             Wp1, bp1, Wp2, bp2);
    merge_kernel<<<148, 512, SMB_TOT>>>(Wm1, bm1, Wm2, bm2, out);
}